// round 1
// baseline (speedup 1.0000x reference)
#include <cuda_runtime.h>
#include <cuda_bf16.h>
#include <math.h>

// Problem constants
#define S   256
#define B   128
#define I   1024
#define H   512
#define G4  (4 * H)            // 2048 gate columns
#define M_TOT (S * B)          // 32768 rows of the input GEMM

// ---------------------------------------------------------------------------
// Device scratch (static allocations are allowed; runtime allocs are not)
// ---------------------------------------------------------------------------
__device__ float g_G[(size_t)M_TOT * G4];   // precomputed x@w_ih^T + bias  (268 MB)
__device__ float g_h[2][B * H];             // double-buffered hidden state
__device__ float g_c[B * H];                // cell state

// ---------------------------------------------------------------------------
// Init: zero h0, c0
// ---------------------------------------------------------------------------
__global__ void init_state() {
    int i = blockIdx.x * blockDim.x + threadIdx.x;
    if (i < B * H) {
        g_h[0][i] = 0.0f;
        g_c[i]    = 0.0f;
    }
}

// ---------------------------------------------------------------------------
// Phase 1: G = X @ W_ih^T + (b_ih + b_hh)
// X: [M_TOT, I] row-major, W: [G4, I] row-major (NT GEMM, both K-major)
// 128x128 block tile, BK=8, 256 threads, 8x8 microtile per thread.
// ---------------------------------------------------------------------------
__global__ __launch_bounds__(256) void gemm_xw(
    const float* __restrict__ X,
    const float* __restrict__ W,
    const float* __restrict__ bih,
    const float* __restrict__ bhh)
{
    __shared__ float As[8][128];
    __shared__ float Bs[8][128];

    const int t  = threadIdx.x;
    const int m0 = blockIdx.y * 128;
    const int n0 = blockIdx.x * 128;

    const int lrow  = t >> 1;            // 0..127
    const int lpart = (t & 1) * 4;       // 0 or 4

    const float* aptr = X + (size_t)(m0 + lrow) * I + lpart;
    const float* bptr = W + (size_t)(n0 + lrow) * I + lpart;

    const int tm = t >> 4;               // 0..15
    const int tn = t & 15;               // 0..15

    float acc[8][8];
#pragma unroll
    for (int i = 0; i < 8; i++)
#pragma unroll
        for (int j = 0; j < 8; j++) acc[i][j] = 0.0f;

    for (int k0 = 0; k0 < I; k0 += 8) {
        float4 av = *(const float4*)(aptr + k0);
        float4 bv = *(const float4*)(bptr + k0);
        __syncthreads();
        As[lpart + 0][lrow] = av.x;
        As[lpart + 1][lrow] = av.y;
        As[lpart + 2][lrow] = av.z;
        As[lpart + 3][lrow] = av.w;
        Bs[lpart + 0][lrow] = bv.x;
        Bs[lpart + 1][lrow] = bv.y;
        Bs[lpart + 2][lrow] = bv.z;
        Bs[lpart + 3][lrow] = bv.w;
        __syncthreads();

#pragma unroll
        for (int kk = 0; kk < 8; kk++) {
            float a[8], b[8];
            float4 a0 = *(const float4*)&As[kk][tm * 8];
            float4 a1 = *(const float4*)&As[kk][tm * 8 + 4];
            float4 b0 = *(const float4*)&Bs[kk][tn * 8];
            float4 b1 = *(const float4*)&Bs[kk][tn * 8 + 4];
            a[0]=a0.x; a[1]=a0.y; a[2]=a0.z; a[3]=a0.w;
            a[4]=a1.x; a[5]=a1.y; a[6]=a1.z; a[7]=a1.w;
            b[0]=b0.x; b[1]=b0.y; b[2]=b0.z; b[3]=b0.w;
            b[4]=b1.x; b[5]=b1.y; b[6]=b1.z; b[7]=b1.w;
#pragma unroll
            for (int i = 0; i < 8; i++)
#pragma unroll
                for (int j = 0; j < 8; j++)
                    acc[i][j] += a[i] * b[j];
        }
    }

    // epilogue: add fused bias, store
    const int n = n0 + tn * 8;
    float bias[8];
#pragma unroll
    for (int j = 0; j < 8; j++) bias[j] = bih[n + j] + bhh[n + j];

#pragma unroll
    for (int i = 0; i < 8; i++) {
        float* dst = g_G + (size_t)(m0 + tm * 8 + i) * G4 + n;
        float4 s0, s1;
        s0.x = acc[i][0] + bias[0];
        s0.y = acc[i][1] + bias[1];
        s0.z = acc[i][2] + bias[2];
        s0.w = acc[i][3] + bias[3];
        s1.x = acc[i][4] + bias[4];
        s1.y = acc[i][5] + bias[5];
        s1.z = acc[i][6] + bias[6];
        s1.w = acc[i][7] + bias[7];
        *(float4*)(dst)     = s0;
        *(float4*)(dst + 4) = s1;
    }
}

// ---------------------------------------------------------------------------
// Phase 2: one LSTM step.
// Block nb (0..127) owns hidden columns n in [nb*4, nb*4+4), i.e. gate cols
// j = g*512 + nb*4 + q for g in 0..3, q in 0..3 (16 "p" columns, p = g*4+q).
// gates[b][p] = G_s[b][j(p)] + sum_k h_in[b][k] * w_hh[j(p)][k]
// Then pointwise LSTM update for its 4 hidden columns, all 128 batch rows.
// h is double-buffered globally so reads (full h) never race writes (own cols).
// ---------------------------------------------------------------------------
__global__ __launch_bounds__(256) void lstm_step(
    const float* __restrict__ Whh, int s)
{
    const int nb = blockIdx.x;          // 0..127
    const int t  = threadIdx.x;         // 0..255
    const int tb = t >> 3;              // 0..31 -> batch group (4 rows)
    const int tg = t & 7;               // 0..7  -> p-pair (tg, tg+8)

    const float* Gs    = g_G + (size_t)s * B * G4;
    const float* h_in  = g_h[s & 1];
    float*       h_out = g_h[(s + 1) & 1];

    __shared__ float h_s[32][128];      // [k][b] transposed chunk of h_in
    __shared__ float w_s[16][33];       // [p][k] (padded: stride 33 avoids conflicts)
    __shared__ float gates_s[16][128];  // [p][b] post-GEMM gate exchange

    const int q  = tg & 3;
    const int g0 = tg >> 2;                         // 0 or 1
    const int j0 = g0 * H + nb * 4 + q;             // gate col for p = tg
    const int j1 = (g0 + 2) * H + nb * 4 + q;       // gate col for p = tg + 8

    float acc0[4], acc1[4];
#pragma unroll
    for (int i = 0; i < 4; i++) {
        int b = tb * 4 + i;
        acc0[i] = Gs[(size_t)b * G4 + j0];
        acc1[i] = Gs[(size_t)b * G4 + j1];
    }

    for (int k0 = 0; k0 < H; k0 += 32) {
        __syncthreads();
        // load h chunk transposed: h_in[b][k0+kk] -> h_s[kk][b]
        {
            const int row  = t >> 1;        // 0..127
            const int part = t & 1;         // 0..1
            const float4* src = (const float4*)(h_in + (size_t)row * H + k0 + part * 16);
#pragma unroll
            for (int c4 = 0; c4 < 4; c4++) {
                float4 v  = src[c4];
                int kk = part * 16 + c4 * 4;
                h_s[kk + 0][row] = v.x;
                h_s[kk + 1][row] = v.y;
                h_s[kk + 2][row] = v.z;
                h_s[kk + 3][row] = v.w;
            }
        }
        // load w chunk: w_s[p][kk] = Whh[j(p)][k0+kk]
        {
            const int p  = t >> 4;          // 0..15
            const int kk = (t & 15) * 2;    // 0..30
            const int jg = p >> 2, jq = p & 3;
            const int j  = jg * H + nb * 4 + jq;
            const float* wrow = Whh + (size_t)j * H + k0;
            w_s[p][kk]     = wrow[kk];
            w_s[p][kk + 1] = wrow[kk + 1];
        }
        __syncthreads();

#pragma unroll 8
        for (int kk = 0; kk < 32; kk++) {
            float4 hv = *(const float4*)&h_s[kk][tb * 4];
            float w0 = w_s[tg][kk];
            float w1 = w_s[tg + 8][kk];
            acc0[0] += hv.x * w0;  acc1[0] += hv.x * w1;
            acc0[1] += hv.y * w0;  acc1[1] += hv.y * w1;
            acc0[2] += hv.z * w0;  acc1[2] += hv.z * w1;
            acc0[3] += hv.w * w0;  acc1[3] += hv.w * w1;
        }
    }

    // exchange gates through smem so each thread can do a full (i,f,g,o) cell
    __syncthreads();
#pragma unroll
    for (int i = 0; i < 4; i++) {
        gates_s[tg][tb * 4 + i]     = acc0[i];
        gates_s[tg + 8][tb * 4 + i] = acc1[i];
    }
    __syncthreads();

    // pointwise LSTM update: 512 (b, q) cells, 2 per thread
#pragma unroll
    for (int cell = t; cell < 512; cell += 256) {
        const int b  = cell >> 2;
        const int qq = cell & 3;
        float gi = gates_s[0 * 4 + qq][b];
        float gf = gates_s[1 * 4 + qq][b];
        float gg = gates_s[2 * 4 + qq][b];
        float go = gates_s[3 * 4 + qq][b];
        float si = 1.0f / (1.0f + __expf(-gi));
        float sf = 1.0f / (1.0f + __expf(-gf));
        float tgh = tanhf(gg);
        float so = 1.0f / (1.0f + __expf(-go));
        const int n   = nb * 4 + qq;
        const int idx = b * H + n;
        float cv = sf * g_c[idx] + si * tgh;
        g_c[idx]   = cv;
        h_out[idx] = so * tanhf(cv);
    }
}

// ---------------------------------------------------------------------------
// Final reduction: sum h_final (in g_h[0], since 256 steps is even) -> out[0]
// Single block => deterministic.
// ---------------------------------------------------------------------------
__global__ __launch_bounds__(1024) void reduce_h(float* __restrict__ out) {
    __shared__ float red[1024];
    const int t = threadIdx.x;
    float s = 0.0f;
    for (int i = t; i < B * H; i += 1024) s += g_h[0][i];
    red[t] = s;
    __syncthreads();
    for (int off = 512; off > 0; off >>= 1) {
        if (t < off) red[t] += red[t + off];
        __syncthreads();
    }
    if (t == 0) out[0] = red[0];
}

// ---------------------------------------------------------------------------
// kernel_launch: graph-capturable sequence (no syncs, no allocs)
// inputs: x [S,B,I], w_ih [4H,I], w_hh [4H,H], b_ih [4H], b_hh [4H]
// output: scalar f32
// ---------------------------------------------------------------------------
extern "C" void kernel_launch(void* const* d_in, const int* in_sizes, int n_in,
                              void* d_out, int out_size) {
    const float* x    = (const float*)d_in[0];
    const float* w_ih = (const float*)d_in[1];
    const float* w_hh = (const float*)d_in[2];
    const float* b_ih = (const float*)d_in[3];
    const float* b_hh = (const float*)d_in[4];
    float* out = (float*)d_out;

    init_state<<<(B * H + 255) / 256, 256>>>();

    dim3 ggrid(G4 / 128, M_TOT / 128);   // (16, 256)
    gemm_xw<<<ggrid, 256>>>(x, w_ih, b_ih, b_hh);

    for (int s = 0; s < S; s++) {
        lstm_step<<<128, 256>>>(w_hh, s);
    }

    reduce_h<<<1, 1024>>>(out);
}

// round 2
// speedup vs baseline: 1.2499x; 1.2499x over previous
#include <cuda_runtime.h>
#include <cuda_bf16.h>
#include <math.h>

// Problem constants
#define S_   256
#define B_   128
#define I_   1024
#define H_   512
#define G4  (4 * H_)            // 2048 gate columns
#define M_TOT (S_ * B_)         // 32768 rows of the input GEMM
#define NBLK 128

// ---------------------------------------------------------------------------
// Device scratch
// ---------------------------------------------------------------------------
__device__ float g_G[(size_t)M_TOT * G4];   // x@w_ih^T + bias  (268 MB)
__device__ float g_h[2][B_ * H_];           // double-buffered hidden state
__device__ int            g_cnt;            // grid barrier arrive counter
__device__ volatile int   g_gen;            // grid barrier generation

// ---------------------------------------------------------------------------
// Init: zero h0 and barrier state (every launch -> replay-deterministic)
// ---------------------------------------------------------------------------
__global__ void init_state() {
    int i = blockIdx.x * blockDim.x + threadIdx.x;
    if (i < B_ * H_) g_h[0][i] = 0.0f;
    if (i == 0) { g_cnt = 0; g_gen = 0; }
}

// ---------------------------------------------------------------------------
// Phase 1: G = X @ W_ih^T + (b_ih + b_hh)   (unchanged, near fp32 roofline)
// ---------------------------------------------------------------------------
__global__ __launch_bounds__(256) void gemm_xw(
    const float* __restrict__ X,
    const float* __restrict__ W,
    const float* __restrict__ bih,
    const float* __restrict__ bhh)
{
    __shared__ float As[8][128];
    __shared__ float Bs[8][128];

    const int t  = threadIdx.x;
    const int m0 = blockIdx.y * 128;
    const int n0 = blockIdx.x * 128;

    const int lrow  = t >> 1;
    const int lpart = (t & 1) * 4;

    const float* aptr = X + (size_t)(m0 + lrow) * I_ + lpart;
    const float* bptr = W + (size_t)(n0 + lrow) * I_ + lpart;

    const int tm = t >> 4;
    const int tn = t & 15;

    float acc[8][8];
#pragma unroll
    for (int i = 0; i < 8; i++)
#pragma unroll
        for (int j = 0; j < 8; j++) acc[i][j] = 0.0f;

    for (int k0 = 0; k0 < I_; k0 += 8) {
        float4 av = *(const float4*)(aptr + k0);
        float4 bv = *(const float4*)(bptr + k0);
        __syncthreads();
        As[lpart + 0][lrow] = av.x;
        As[lpart + 1][lrow] = av.y;
        As[lpart + 2][lrow] = av.z;
        As[lpart + 3][lrow] = av.w;
        Bs[lpart + 0][lrow] = bv.x;
        Bs[lpart + 1][lrow] = bv.y;
        Bs[lpart + 2][lrow] = bv.z;
        Bs[lpart + 3][lrow] = bv.w;
        __syncthreads();

#pragma unroll
        for (int kk = 0; kk < 8; kk++) {
            float a[8], b[8];
            float4 a0 = *(const float4*)&As[kk][tm * 8];
            float4 a1 = *(const float4*)&As[kk][tm * 8 + 4];
            float4 b0 = *(const float4*)&Bs[kk][tn * 8];
            float4 b1 = *(const float4*)&Bs[kk][tn * 8 + 4];
            a[0]=a0.x; a[1]=a0.y; a[2]=a0.z; a[3]=a0.w;
            a[4]=a1.x; a[5]=a1.y; a[6]=a1.z; a[7]=a1.w;
            b[0]=b0.x; b[1]=b0.y; b[2]=b0.z; b[3]=b0.w;
            b[4]=b1.x; b[5]=b1.y; b[6]=b1.z; b[7]=b1.w;
#pragma unroll
            for (int i = 0; i < 8; i++)
#pragma unroll
                for (int j = 0; j < 8; j++)
                    acc[i][j] += a[i] * b[j];
        }
    }

    const int n = n0 + tn * 8;
    float bias[8];
#pragma unroll
    for (int j = 0; j < 8; j++) bias[j] = bih[n + j] + bhh[n + j];

#pragma unroll
    for (int i = 0; i < 8; i++) {
        float* dst = g_G + (size_t)(m0 + tm * 8 + i) * G4 + n;
        float4 s0, s1;
        s0.x = acc[i][0] + bias[0];
        s0.y = acc[i][1] + bias[1];
        s0.z = acc[i][2] + bias[2];
        s0.w = acc[i][3] + bias[3];
        s1.x = acc[i][4] + bias[4];
        s1.y = acc[i][5] + bias[5];
        s1.z = acc[i][6] + bias[6];
        s1.w = acc[i][7] + bias[7];
        *(float4*)(dst)     = s0;
        *(float4*)(dst + 4) = s1;
    }
}

// ---------------------------------------------------------------------------
// Phase 2: persistent LSTM recurrence. One kernel, 128 co-resident blocks,
// software grid barrier per step.
//
// Block bid: cg = bid>>2 (owns hidden cols [cg*16, cg*16+16) => 64 gate cols
//            across the 4 gates), bg = bid&3 (owns batches [bg*32, bg*32+32)).
// w_hh tile (64x512) staged into smem ONCE (transposed to w_t[k][p]).
// Per step: full h tile (32x512) staged to smem; 4096 FFMA/thread; pointwise
// update with c held in registers; h written to double-buffered global.
// ---------------------------------------------------------------------------
// smem layout (floats):
//   w_t : [512][64]          32768 floats
//   h_s : [32][520]          16640 floats (pad 520 keeps 16B align)
//   gt  : [64][33]            2112 floats
#define SM_WT   0
#define SM_HS   32768
#define SM_GT   (32768 + 32 * 520)
#define SM_FLOATS (SM_GT + 64 * 33)

__global__ __launch_bounds__(256, 1) void lstm_persist(const float* __restrict__ Whh)
{
    extern __shared__ float sm[];
    float* w_t = sm + SM_WT;
    float* h_s = sm + SM_HS;
    float* gt  = sm + SM_GT;

    const int bid = blockIdx.x;
    const int cg  = bid >> 2;      // 0..31 column group
    const int bg  = bid & 3;       // 0..3  batch group
    const int t   = threadIdx.x;   // 0..255
    const int jg  = t & 15;        // 16 col sub-groups (4 cols each)
    const int bgp = t >> 4;        // 16 batch pairs
    const int b0  = 2 * bgp;
    const int b1  = b0 + 1;

    // ---- stage W tile transposed: w_t[k][p] = Whh[j(p)][k], one time ----
    {
        const int p  = t >> 2;                 // 0..63
        const int kq = (t & 3) * 128;          // 0,128,256,384
        const int gj = (p >> 4) * H_ + cg * 16 + (p & 15);
        const float* wr = Whh + (size_t)gj * H_ + kq;
#pragma unroll 8
        for (int i = 0; i < 128; i += 4) {
            float4 v = *(const float4*)(wr + i);
            w_t[(kq + i + 0) * 64 + p] = v.x;
            w_t[(kq + i + 1) * 64 + p] = v.y;
            w_t[(kq + i + 2) * 64 + p] = v.z;
            w_t[(kq + i + 3) * 64 + p] = v.w;
        }
    }

    // ---- fixed cell mapping for pointwise phase; c lives in registers ----
    const int cc0 = 2 * t,     cc1 = 2 * t + 1;
    const int nn0 = cc0 >> 5,  bl0 = cc0 & 31;
    const int nn1 = cc1 >> 5,  bl1 = cc1 & 31;
    float creg0 = 0.0f, creg1 = 0.0f;

    // G address pieces for this thread
    const int gsel = jg >> 2;                              // which gate pair half
    const int joff = gsel * H_ + cg * 16 + 4 * (jg & 3);   // NOTE: covers g=0,1
    // p = 4*jg+jj spans [0,64): g = p>>4 in {0,1,2,3}; 4*(jg)*... recompute:
    // actually p>>4 = jg>>2, p&15 = 4*(jg&3)+jj  -> joff above with gsel=jg>>2.

    __syncthreads();

    for (int s = 0; s < S_; ++s) {
        // ---- prefetch this step's G slice (independent of h) ----
        const float* Gs = g_G + (size_t)s * (B_ * G4);
        float4 ga = *(const float4*)(Gs + (size_t)(bg * 32 + b0) * G4 + joff);
        float4 gb = *(const float4*)(Gs + (size_t)(bg * 32 + b1) * G4 + joff);

        // ---- stage h tile [32][512] into smem ----
        const float* h_in = g_h[s & 1];
        {
            const int row = t >> 3;            // 0..31
            const int kq2 = (t & 7) * 64;      // 0..448
            const float* src = h_in + (size_t)(bg * 32 + row) * H_ + kq2;
            float* dst = h_s + row * 520 + kq2;
#pragma unroll 4
            for (int i = 0; i < 64; i += 4)
                *(float4*)(dst + i) = *(const float4*)(src + i);
        }
        __syncthreads();

        // ---- GEMM: acc[jj][bb] = G + sum_k w[p][k] * h[b][k] ----
        float a00 = ga.x, a10 = ga.y, a20 = ga.z, a30 = ga.w;
        float a01 = gb.x, a11 = gb.y, a21 = gb.z, a31 = gb.w;

        const float* hr0 = h_s + b0 * 520;
        const float* hr1 = h_s + b1 * 520;
        const float* wp  = w_t + jg * 4;

#pragma unroll 2
        for (int k = 0; k < H_; k += 4) {
            float4 h0 = *(const float4*)(hr0 + k);
            float4 h1 = *(const float4*)(hr1 + k);
            float4 w;
            w = *(const float4*)(wp + (k + 0) * 64);
            a00 += w.x * h0.x; a10 += w.y * h0.x; a20 += w.z * h0.x; a30 += w.w * h0.x;
            a01 += w.x * h1.x; a11 += w.y * h1.x; a21 += w.z * h1.x; a31 += w.w * h1.x;
            w = *(const float4*)(wp + (k + 1) * 64);
            a00 += w.x * h0.y; a10 += w.y * h0.y; a20 += w.z * h0.y; a30 += w.w * h0.y;
            a01 += w.x * h1.y; a11 += w.y * h1.y; a21 += w.z * h1.y; a31 += w.w * h1.y;
            w = *(const float4*)(wp + (k + 2) * 64);
            a00 += w.x * h0.z; a10 += w.y * h0.z; a20 += w.z * h0.z; a30 += w.w * h0.z;
            a01 += w.x * h1.z; a11 += w.y * h1.z; a21 += w.z * h1.z; a31 += w.w * h1.z;
            w = *(const float4*)(wp + (k + 3) * 64);
            a00 += w.x * h0.w; a10 += w.y * h0.w; a20 += w.z * h0.w; a30 += w.w * h0.w;
            a01 += w.x * h1.w; a11 += w.y * h1.w; a21 += w.z * h1.w; a31 += w.w * h1.w;
        }

        // ---- exchange gates via smem (p = 4*jg+jj == g*16+nn identity) ----
        gt[(4 * jg + 0) * 33 + b0] = a00;  gt[(4 * jg + 0) * 33 + b1] = a01;
        gt[(4 * jg + 1) * 33 + b0] = a10;  gt[(4 * jg + 1) * 33 + b1] = a11;
        gt[(4 * jg + 2) * 33 + b0] = a20;  gt[(4 * jg + 2) * 33 + b1] = a21;
        gt[(4 * jg + 3) * 33 + b0] = a30;  gt[(4 * jg + 3) * 33 + b1] = a31;
        __syncthreads();

        // ---- pointwise LSTM update (2 cells per thread, c in registers) ----
        float* h_out = g_h[(s + 1) & 1];
        {
            float gi = gt[(0 * 16 + nn0) * 33 + bl0];
            float gf = gt[(1 * 16 + nn0) * 33 + bl0];
            float gg = gt[(2 * 16 + nn0) * 33 + bl0];
            float go = gt[(3 * 16 + nn0) * 33 + bl0];
            float si = 1.0f / (1.0f + __expf(-gi));
            float sf = 1.0f / (1.0f + __expf(-gf));
            float tg = tanhf(gg);
            float so = 1.0f / (1.0f + __expf(-go));
            creg0 = sf * creg0 + si * tg;
            h_out[(size_t)(bg * 32 + bl0) * H_ + cg * 16 + nn0] = so * tanhf(creg0);
        }
        {
            float gi = gt[(0 * 16 + nn1) * 33 + bl1];
            float gf = gt[(1 * 16 + nn1) * 33 + bl1];
            float gg = gt[(2 * 16 + nn1) * 33 + bl1];
            float go = gt[(3 * 16 + nn1) * 33 + bl1];
            float si = 1.0f / (1.0f + __expf(-gi));
            float sf = 1.0f / (1.0f + __expf(-gf));
            float tg = tanhf(gg);
            float so = 1.0f / (1.0f + __expf(-go));
            creg1 = sf * creg1 + si * tg;
            h_out[(size_t)(bg * 32 + bl1) * H_ + cg * 16 + nn1] = so * tanhf(creg1);
        }

        // ---- grid barrier: all h_out writes visible before next step ----
        __threadfence();
        __syncthreads();
        if (t == 0) {
            int old = atomicAdd(&g_cnt, 1);
            if (old == NBLK - 1) {
                atomicExch(&g_cnt, 0);
                __threadfence();
                g_gen = s + 1;
            } else {
                while (g_gen <= s) { }
                __threadfence();
            }
        }
        __syncthreads();
    }
}

// ---------------------------------------------------------------------------
// Final reduction: sum h_final (g_h[0] after 256 steps) -> out[0]
// ---------------------------------------------------------------------------
__global__ __launch_bounds__(1024) void reduce_h(float* __restrict__ out) {
    __shared__ float red[1024];
    const int t = threadIdx.x;
    float s = 0.0f;
    for (int i = t; i < B_ * H_; i += 1024) s += g_h[0][i];
    red[t] = s;
    __syncthreads();
    for (int off = 512; off > 0; off >>= 1) {
        if (t < off) red[t] += red[t + off];
        __syncthreads();
    }
    if (t == 0) out[0] = red[0];
}

// ---------------------------------------------------------------------------
// kernel_launch
// ---------------------------------------------------------------------------
extern "C" void kernel_launch(void* const* d_in, const int* in_sizes, int n_in,
                              void* d_out, int out_size) {
    const float* x    = (const float*)d_in[0];
    const float* w_ih = (const float*)d_in[1];
    const float* w_hh = (const float*)d_in[2];
    const float* b_ih = (const float*)d_in[3];
    const float* b_hh = (const float*)d_in[4];
    float* out = (float*)d_out;

    static_assert(SM_FLOATS * 4 <= 227 * 1024, "smem overflow");
    cudaFuncSetAttribute(lstm_persist,
                         cudaFuncAttributeMaxDynamicSharedMemorySize,
                         SM_FLOATS * sizeof(float));

    init_state<<<(B_ * H_ + 255) / 256, 256>>>();

    dim3 ggrid(G4 / 128, M_TOT / 128);   // (16, 256)
    gemm_xw<<<ggrid, 256>>>(x, w_ih, b_ih, b_hh);

    lstm_persist<<<NBLK, 256, SM_FLOATS * sizeof(float)>>>(w_hh);

    reduce_h<<<1, 1024>>>(out);
}